// round 8
// baseline (speedup 1.0000x reference)
#include <cuda_runtime.h>
#include <cstdint>

// Problem constants
#define B_ROWS 4096
#define NDOM 8
#define D0 1024
#define D1 1024
#define D2 512
#define D3 256
#define MAXT128 40
#define MAXT64 72

// ---------------- device scratch ----------------
__device__ int   g_perm[B_ROWS];
__device__ int   g_off[NDOM + 1];
__device__ int   g_tile_d128[MAXT128];
__device__ int   g_tile_m128[MAXT128];
__device__ int   g_nt128;
__device__ int   g_tile_d64[MAXT64];
__device__ int   g_tile_m64[MAXT64];
__device__ int   g_nt64;
__device__ float g_h1[B_ROWS * D1];
__device__ float g_h2[B_ROWS * D2];

__device__ __forceinline__ float tf32r(float x) {
    uint32_t u;
    asm("cvt.rna.tf32.f32 %0, %1;" : "=r"(u) : "f"(x));
    return __uint_as_float(u);
}

#define MMA_TF32(d, a0, a1, a2, a3, b0, b1)                                   \
    asm volatile(                                                             \
        "mma.sync.aligned.m16n8k8.row.col.f32.tf32.tf32.f32 "                 \
        "{%0,%1,%2,%3}, {%4,%5,%6,%7}, {%8,%9}, {%0,%1,%2,%3};"               \
        : "+f"((d)[0]), "+f"((d)[1]), "+f"((d)[2]), "+f"((d)[3])              \
        : "r"(a0), "r"(a1), "r"(a2), "r"(a3), "r"(b0), "r"(b1))

// ---------------- permutation + tile lists ----------------
__global__ void build_perm(const int* __restrict__ ind) {
    __shared__ int cnt[NDOM];
    __shared__ int cur[NDOM];
    int t = threadIdx.x;
    if (t < NDOM) cnt[t] = 0;
    __syncthreads();
    for (int i = t; i < B_ROWS; i += blockDim.x) atomicAdd(&cnt[ind[i]], 1);
    __syncthreads();
    if (t == 0) {
        int s = 0;
        for (int d = 0; d < NDOM; d++) { g_off[d] = s; cur[d] = s; s += cnt[d]; }
        g_off[NDOM] = s;
        int n128 = 0, n64 = 0;
        for (int d = 0; d < NDOM; d++) {
            int len = g_off[d + 1] - g_off[d];
            for (int m0 = 0; m0 < len; m0 += 128) {
                g_tile_d128[n128] = d; g_tile_m128[n128] = m0; n128++;
            }
            for (int m0 = 0; m0 < len; m0 += 64) {
                g_tile_d64[n64] = d; g_tile_m64[n64] = m0; n64++;
            }
        }
        g_nt128 = n128;
        g_nt64  = n64;
    }
    __syncthreads();
    for (int i = t; i < B_ROWS; i += blockDim.x) {
        int d = ind[i];
        int p = atomicAdd(&cur[d], 1);
        g_perm[p] = i;
    }
}

// ---------------- smem layout (floats), templated on MTILE ----------------
// A fragments, MMA-permuted: [buf][split][mtile 0..NMT-1][lane][20]
// B fragments, packed per (nw,ks): [buf][split][nw][ks][lane][12] (8 used)
//   value W(k,n): lane=(n&7)*4+(k&3), slot=((n>>3)&3)*2+((k>>2)&1)
#define BF_FLOATS (2 * 2 * 4 * 4 * 384)   // 24576 floats = 96KB

template <int MTILE> struct SML {
    static constexpr int NMT   = MTILE / 16;
    static constexpr int AF_SZ = 2 * 2 * NMT * 640;
    static constexpr int SM_B  = AF_SZ;
    static constexpr int SM_RI = AF_SZ + BF_FLOATS;
    static constexpr int SM_BI = SM_RI + MTILE;
    static constexpr int BYTES = (SM_BI + 128) * 4;
};

// ---------------- 3xTF32 mma.sync grouped GEMM, fused weight build ----------
// Block tile MTILE x 128, K-chunk 32, double-buffered, 256 threads / 8 warps
// (2M x 4N), warp tile (MTILE/2) x 32.
template <int LAYER, int MTILE>
__global__ __launch_bounds__(256, 1)
void gemm_mma(const float* __restrict__ xin, const float* __restrict__ sk,
              const float* __restrict__ dkk, const float* __restrict__ sb,
              const float* __restrict__ db, float* __restrict__ outp) {
    constexpr int K = (LAYER == 0) ? D0 : (LAYER == 1) ? D1 : D2;
    constexpr int N = (LAYER == 0) ? D1 : (LAYER == 1) ? D2 : D3;
    constexpr int NCH = K / 32;
    constexpr int NMT = MTILE / 16;      // 16-row A frag tiles per block
    constexpr int MT_W = NMT / 2;        // per warp
    constexpr int AIT = MTILE / 32;      // A loader items per thread
    using L = SML<MTILE>;

    const int tyb = blockIdx.y;
    const int ntl = (MTILE == 128) ? g_nt128 : g_nt64;
    if (tyb >= ntl) return;
    const int d   = (MTILE == 128) ? g_tile_d128[tyb] : g_tile_d64[tyb];
    const int m0  = (MTILE == 128) ? g_tile_m128[tyb] : g_tile_m64[tyb];
    const int off = g_off[d];
    const int len = g_off[d + 1] - off;
    const int n0  = blockIdx.x * 128;

    extern __shared__ float smf[];
    int*   rowIdx = (int*)(smf + L::SM_RI);
    float* biasS  = smf + L::SM_BI;

    const int tid  = threadIdx.x;
    const int lane = tid & 31;
    const int w    = tid >> 5;
    const int mw   = w >> 2;
    const int nw   = w & 3;
    const int grp  = lane >> 2;
    const int tig  = lane & 3;

    if (tid < MTILE) {
        int r = m0 + tid;
        int row = -1;
        if (r < len) row = (LAYER == 0) ? g_perm[off + r] : (off + r);
        rowIdx[tid] = row;
    }
    if (tid >= 128 && tid < 160) {
        int q = tid - 128;
        float4 a = *(const float4*)(sb + n0 + q * 4);
        float4 b = *(const float4*)(db + (size_t)d * N + n0 + q * 4);
        a.x += b.x; a.y += b.y; a.z += b.z; a.w += b.w;
        *(float4*)(biasS + q * 4) = a;
    }
    __syncthreads();

    const float* Ap  = (LAYER == 0) ? xin : (LAYER == 1) ? g_h1 : g_h2;
    float*       Cp  = (LAYER == 0) ? g_h1 : (LAYER == 1) ? g_h2 : outp;
    const float* dkd = dkk + (size_t)d * K * N;

    float acc[MT_W][4][4];
#pragma unroll
    for (int i = 0; i < MT_W; i++)
#pragma unroll
        for (int j = 0; j < 4; j++)
#pragma unroll
            for (int q = 0; q < 4; q++) acc[i][j][q] = 0.f;

    // loader coords
    const int ldr = tid >> 3;           // 0..31 (A row base & B k-row)
    const int fq  = tid & 7;
    // B writer constants (k = ldr)
    const int ksw    = ldr >> 3;
    const int tigw12 = (ldr & 3) * 12;
    const int halfk  = (ldr >> 2) & 1;

    int rws[AIT];
#pragma unroll
    for (int i = 0; i < AIT; i++) rws[i] = rowIdx[ldr + 32 * i];

    float4 avA[AIT], avW[4];

#define LOADC(c)                                                              \
    {                                                                         \
        const int k0 = (c) * 32;                                              \
        _Pragma("unroll")                                                     \
        for (int i = 0; i < AIT; i++) {                                       \
            int rr = rws[i];                                                  \
            avA[i] = (rr >= 0)                                                \
                ? *(const float4*)(Ap + (size_t)rr * K + k0 + fq * 4)         \
                : make_float4(0.f, 0.f, 0.f, 0.f);                            \
        }                                                                     \
        _Pragma("unroll")                                                     \
        for (int i = 0; i < 4; i++) {                                         \
            int co = n0 + (fq + 8 * i) * 4;                                   \
            float4 s = *(const float4*)(sk  + (size_t)(k0 + ldr) * N + co);   \
            float4 t = *(const float4*)(dkd + (size_t)(k0 + ldr) * N + co);   \
            avW[i].x = s.x * t.x; avW[i].y = s.y * t.y;                       \
            avW[i].z = s.z * t.z; avW[i].w = s.w * t.w;                       \
        }                                                                     \
    }

#define STOREC(c)                                                             \
    {                                                                         \
        const int buf = (c) & 1;                                              \
        const int ks  = fq >> 1;                                              \
        const int kh2 = (fq & 1) * 2;                                         \
        _Pragma("unroll")                                                     \
        for (int i = 0; i < AIT; i++) {                                       \
            int row = ldr + 32 * i;                                           \
            int mt  = row >> 4;                                               \
            int l0  = (row & 7) * 4;                                          \
            int ai  = ((row & 15) >= 8 ? 1 : 0) + kh2;                        \
            float* pb = smf + ((buf * 2 + 0) * NMT + mt) * 640 + ks * 4 + ai; \
            float* ps = smf + ((buf * 2 + 1) * NMT + mt) * 640 + ks * 4 + ai; \
            float4 v = avA[i];                                                \
            float bx = tf32r(v.x), by = tf32r(v.y);                           \
            float bz = tf32r(v.z), bw = tf32r(v.w);                           \
            pb[(l0 + 0) * 20] = bx; ps[(l0 + 0) * 20] = tf32r(v.x - bx);      \
            pb[(l0 + 1) * 20] = by; ps[(l0 + 1) * 20] = tf32r(v.y - by);      \
            pb[(l0 + 2) * 20] = bz; ps[(l0 + 2) * 20] = tf32r(v.z - bz);      \
            pb[(l0 + 3) * 20] = bw; ps[(l0 + 3) * 20] = tf32r(v.w - bw);      \
        }                                                                     \
        _Pragma("unroll")                                                     \
        for (int i = 0; i < 4; i++) {                                         \
            float4 wv = avW[i];                                               \
            float wb[4], ws[4];                                               \
            wb[0] = tf32r(wv.x); ws[0] = tf32r(wv.x - wb[0]);                 \
            wb[1] = tf32r(wv.y); ws[1] = tf32r(wv.y - wb[1]);                 \
            wb[2] = tf32r(wv.z); ws[2] = tf32r(wv.z - wb[2]);                 \
            wb[3] = tf32r(wv.w); ws[3] = tf32r(wv.w - wb[3]);                 \
            float* b0 = smf + L::SM_B +                                       \
                ((buf * 2 + 0) * 16 + i * 4 + ksw) * 384 + tigw12 + halfk;    \
            float* s0 = smf + L::SM_B +                                       \
                ((buf * 2 + 1) * 16 + i * 4 + ksw) * 384 + tigw12 + halfk;    \
            _Pragma("unroll")                                                 \
            for (int j = 0; j < 4; j++) {                                     \
                int nl = 4 * fq + j;                                          \
                int o = (nl & 7) * 48 + ((nl >> 3) & 3) * 2;                  \
                b0[o] = wb[j];                                                \
                s0[o] = ws[j];                                                \
            }                                                                 \
        }                                                                     \
    }

    LOADC(0);
    STOREC(0);

    for (int c = 0; c < NCH; c++) {
        const int buf = c & 1;
        __syncthreads();
        if (c + 1 < NCH) LOADC(c + 1);

        const float* afb = smf + ((buf * 2 + 0) * NMT + mw * MT_W) * 640 + lane * 20;
        const float* afs = smf + ((buf * 2 + 1) * NMT + mw * MT_W) * 640 + lane * 20;
        const float* bfb = smf + L::SM_B + ((buf * 2 + 0) * 16 + nw * 4) * 384 + lane * 12;
        const float* bfs = smf + L::SM_B + ((buf * 2 + 1) * 16 + nw * 4) * 384 + lane * 12;
#pragma unroll
        for (int ks = 0; ks < 4; ks++) {
            uint4 fab[MT_W], fas[MT_W];
#pragma unroll
            for (int mt = 0; mt < MT_W; mt++) {
                fab[mt] = *(const uint4*)(afb + mt * 640 + ks * 4);
                fas[mt] = *(const uint4*)(afs + mt * 640 + ks * 4);
            }
            float4 qb0 = *(const float4*)(bfb + ks * 384);
            float4 qb1 = *(const float4*)(bfb + ks * 384 + 4);
            float4 qs0 = *(const float4*)(bfs + ks * 384);
            float4 qs1 = *(const float4*)(bfs + ks * 384 + 4);
            float bbv[4][2] = {{qb0.x, qb0.y}, {qb0.z, qb0.w},
                               {qb1.x, qb1.y}, {qb1.z, qb1.w}};
            float bsv[4][2] = {{qs0.x, qs0.y}, {qs0.z, qs0.w},
                               {qs1.x, qs1.y}, {qs1.z, qs1.w}};
#pragma unroll
            for (int nt = 0; nt < 4; nt++) {
                uint32_t bb0 = __float_as_uint(bbv[nt][0]);
                uint32_t bb1 = __float_as_uint(bbv[nt][1]);
                uint32_t bs0 = __float_as_uint(bsv[nt][0]);
                uint32_t bs1 = __float_as_uint(bsv[nt][1]);
#pragma unroll
                for (int mt = 0; mt < MT_W; mt++) {
                    MMA_TF32(acc[mt][nt], fab[mt].x, fab[mt].y, fab[mt].z, fab[mt].w, bb0, bb1);
                    MMA_TF32(acc[mt][nt], fab[mt].x, fab[mt].y, fab[mt].z, fab[mt].w, bs0, bs1);
                    MMA_TF32(acc[mt][nt], fas[mt].x, fas[mt].y, fas[mt].z, fas[mt].w, bb0, bb1);
                }
            }
        }
        if (c + 1 < NCH) STOREC(c + 1);
    }

    // ---------------- epilogue: bias + relu + (scatter) store ----------------
#pragma unroll
    for (int mt = 0; mt < MT_W; mt++) {
#pragma unroll
        for (int half = 0; half < 2; half++) {
            int mrow = mw * (MTILE / 2) + mt * 16 + grp + half * 8;
            int r = m0 + mrow;
            if (r < len) {
                int orow = (LAYER == 2) ? g_perm[off + r] : (off + r);
                float* crow = Cp + (size_t)orow * N + n0;
#pragma unroll
                for (int nt = 0; nt < 4; nt++) {
                    int col = nw * 32 + nt * 8 + 2 * tig;
                    float2 o;
                    o.x = fmaxf(acc[mt][nt][half * 2 + 0] + biasS[col], 0.f);
                    o.y = fmaxf(acc[mt][nt][half * 2 + 1] + biasS[col + 1], 0.f);
                    *(float2*)(crow + col) = o;
                }
            }
        }
    }
}

// ---------------- launch ----------------
extern "C" void kernel_launch(void* const* d_in, const int* in_sizes, int n_in,
                              void* d_out, int out_size) {
    const float* x   = (const float*)d_in[0];
    const int*   ind = (const int*)  d_in[1];
    const float* sk0 = (const float*)d_in[2];
    const float* sb0 = (const float*)d_in[3];
    const float* dk0 = (const float*)d_in[4];
    const float* db0 = (const float*)d_in[5];
    const float* sk1 = (const float*)d_in[6];
    const float* sb1 = (const float*)d_in[7];
    const float* dk1 = (const float*)d_in[8];
    const float* db1 = (const float*)d_in[9];
    const float* sk2 = (const float*)d_in[10];
    const float* sb2 = (const float*)d_in[11];
    const float* dk2 = (const float*)d_in[12];
    const float* db2 = (const float*)d_in[13];
    float* out = (float*)d_out;

    constexpr int SM128 = SML<128>::BYTES;
    constexpr int SM64  = SML<64>::BYTES;
    cudaFuncSetAttribute(gemm_mma<0, 128>, cudaFuncAttributeMaxDynamicSharedMemorySize, SM128);
    cudaFuncSetAttribute(gemm_mma<1, 128>, cudaFuncAttributeMaxDynamicSharedMemorySize, SM128);
    cudaFuncSetAttribute(gemm_mma<2, 64>,  cudaFuncAttributeMaxDynamicSharedMemorySize, SM64);

    build_perm<<<1, 256>>>(ind);

    gemm_mma<0, 128><<<dim3(D1 / 128, MAXT128), 256, SM128>>>(x, sk0, dk0, sb0, db0, nullptr);
    gemm_mma<1, 128><<<dim3(D2 / 128, MAXT128), 256, SM128>>>(nullptr, sk1, dk1, sb1, db1, nullptr);
    gemm_mma<2, 64><<<dim3(D3 / 128, MAXT64), 256, SM64>>>(nullptr, sk2, dk2, sb2, db2, out);
}

// round 9
// speedup vs baseline: 1.5807x; 1.5807x over previous
#include <cuda_runtime.h>
#include <cuda_bf16.h>
#include <cstdint>

// Problem constants
#define B_ROWS 4096
#define NDOM 8
#define D0 1024
#define D1 1024
#define D2 512
#define D3 256
#define MAXT128 40
#define MAXT64 72

// ---------------- device scratch ----------------
__device__ int   g_perm[B_ROWS];
__device__ int   g_off[NDOM + 1];
__device__ int   g_tile_d128[MAXT128];
__device__ int   g_tile_m128[MAXT128];
__device__ int   g_nt128;
__device__ int   g_tile_d64[MAXT64];
__device__ int   g_tile_m64[MAXT64];
__device__ int   g_nt64;
__device__ float g_h1[B_ROWS * D1];
__device__ float g_h2[B_ROWS * D2];

#define MMA_BF16(d, a, b0, b1)                                                \
    asm volatile(                                                             \
        "mma.sync.aligned.m16n8k16.row.col.f32.bf16.bf16.f32 "                \
        "{%0,%1,%2,%3}, {%4,%5,%6,%7}, {%8,%9}, {%0,%1,%2,%3};"               \
        : "+f"((d)[0]), "+f"((d)[1]), "+f"((d)[2]), "+f"((d)[3])              \
        : "r"((a)[0]), "r"((a)[1]), "r"((a)[2]), "r"((a)[3]),                 \
          "r"(b0), "r"(b1))

#define LDSM_X4(r, addr)                                                      \
    asm volatile("ldmatrix.sync.aligned.m8n8.x4.shared.b16 "                  \
                 "{%0,%1,%2,%3}, [%4];"                                       \
                 : "=r"((r)[0]), "=r"((r)[1]), "=r"((r)[2]), "=r"((r)[3])     \
                 : "r"(addr))

#define LDSM_X4T(r0, r1, r2, r3, addr)                                        \
    asm volatile("ldmatrix.sync.aligned.m8n8.x4.trans.shared.b16 "            \
                 "{%0,%1,%2,%3}, [%4];"                                       \
                 : "=r"(r0), "=r"(r1), "=r"(r2), "=r"(r3)                     \
                 : "r"(addr))

__device__ __forceinline__ void split_store(char* pHi, char* pLo, float4 v) {
    __nv_bfloat162 h01 = __floats2bfloat162_rn(v.x, v.y);
    __nv_bfloat162 h23 = __floats2bfloat162_rn(v.z, v.w);
    float2 f01 = __bfloat1622float2(h01);
    float2 f23 = __bfloat1622float2(h23);
    __nv_bfloat162 l01 = __floats2bfloat162_rn(v.x - f01.x, v.y - f01.y);
    __nv_bfloat162 l23 = __floats2bfloat162_rn(v.z - f23.x, v.w - f23.y);
    uint2 hv, lv;
    hv.x = *(uint32_t*)&h01; hv.y = *(uint32_t*)&h23;
    lv.x = *(uint32_t*)&l01; lv.y = *(uint32_t*)&l23;
    *(uint2*)pHi = hv;
    *(uint2*)pLo = lv;
}

// ---------------- permutation + tile lists ----------------
__global__ void build_perm(const int* __restrict__ ind) {
    __shared__ int cnt[NDOM];
    __shared__ int cur[NDOM];
    int t = threadIdx.x;
    if (t < NDOM) cnt[t] = 0;
    __syncthreads();
    for (int i = t; i < B_ROWS; i += blockDim.x) atomicAdd(&cnt[ind[i]], 1);
    __syncthreads();
    if (t == 0) {
        int s = 0;
        for (int d = 0; d < NDOM; d++) { g_off[d] = s; cur[d] = s; s += cnt[d]; }
        g_off[NDOM] = s;
        int n128 = 0, n64 = 0;
        for (int d = 0; d < NDOM; d++) {
            int len = g_off[d + 1] - g_off[d];
            for (int m0 = 0; m0 < len; m0 += 128) {
                g_tile_d128[n128] = d; g_tile_m128[n128] = m0; n128++;
            }
            for (int m0 = 0; m0 < len; m0 += 64) {
                g_tile_d64[n64] = d; g_tile_m64[n64] = m0; n64++;
            }
        }
        g_nt128 = n128;
        g_nt64  = n64;
    }
    __syncthreads();
    for (int i = t; i < B_ROWS; i += blockDim.x) {
        int d = ind[i];
        int p = atomicAdd(&cur[d], 1);
        g_perm[p] = i;
    }
}

// ---------------- smem layout (bytes), templated on MTILE ----------------
// A: [buf][split][row<MTILE] rows of 32 bf16 (64B data, 80B stride)
// B: [buf][split][k<32]      rows of 128 bf16 (256B data, 272B stride)
template <int MTILE> struct SML {
    static constexpr int ABYTES = 4 * MTILE * 80;
    static constexpr int BBYTES = 4 * 32 * 272;          // 34816
    static constexpr int RI     = ABYTES + BBYTES;
    static constexpr int BI     = RI + MTILE * 4;
    static constexpr int BYTES  = BI + 512;
};

// ---------------- bf16 split (3-product) grouped GEMM ----------------
// Block tile MTILE x 128, K-chunk 32, double-buffered, 256 threads / 8 warps
// (2M x 4N), warp tile (MTILE/2) x 32. Fragments via ldmatrix.
template <int LAYER, int MTILE>
__global__ __launch_bounds__(256, 1)
void gemm_mma(const float* __restrict__ xin, const float* __restrict__ sk,
              const float* __restrict__ dkk, const float* __restrict__ sb,
              const float* __restrict__ db, float* __restrict__ outp) {
    constexpr int K = (LAYER == 0) ? D0 : (LAYER == 1) ? D1 : D2;
    constexpr int N = (LAYER == 0) ? D1 : (LAYER == 1) ? D2 : D3;
    constexpr int NCH = K / 32;
    constexpr int MT_W = MTILE / 32;     // m16 tiles per warp
    constexpr int AIT = MTILE / 32;      // A loader items per thread
    using L = SML<MTILE>;

    const int tyb = blockIdx.y;
    const int ntl = (MTILE == 128) ? g_nt128 : g_nt64;
    if (tyb >= ntl) return;
    const int d   = (MTILE == 128) ? g_tile_d128[tyb] : g_tile_d64[tyb];
    const int m0  = (MTILE == 128) ? g_tile_m128[tyb] : g_tile_m64[tyb];
    const int off = g_off[d];
    const int len = g_off[d + 1] - off;
    const int n0  = blockIdx.x * 128;

    extern __shared__ char smc[];
    int*   rowIdx = (int*)(smc + L::RI);
    float* biasS  = (float*)(smc + L::BI);

    const int tid  = threadIdx.x;
    const int lane = tid & 31;
    const int w    = tid >> 5;
    const int mw   = w >> 2;
    const int nw   = w & 3;
    const int grp  = lane >> 2;
    const int tig  = lane & 3;

    if (tid < MTILE) {
        int r = m0 + tid;
        int row = -1;
        if (r < len) row = (LAYER == 0) ? g_perm[off + r] : (off + r);
        rowIdx[tid] = row;
    }
    if (tid >= 128 && tid < 160) {
        int q = tid - 128;
        float4 a = *(const float4*)(sb + n0 + q * 4);
        float4 b = *(const float4*)(db + (size_t)d * N + n0 + q * 4);
        a.x += b.x; a.y += b.y; a.z += b.z; a.w += b.w;
        *(float4*)(biasS + q * 4) = a;
    }
    __syncthreads();

    const float* Ap  = (LAYER == 0) ? xin : (LAYER == 1) ? g_h1 : g_h2;
    float*       Cp  = (LAYER == 0) ? g_h1 : (LAYER == 1) ? g_h2 : outp;
    const float* dkd = dkk + (size_t)d * K * N;

    float acc[MT_W][4][4];
#pragma unroll
    for (int i = 0; i < MT_W; i++)
#pragma unroll
        for (int j = 0; j < 4; j++)
#pragma unroll
            for (int q = 0; q < 4; q++) acc[i][j][q] = 0.f;

    // loader coords
    const int ldr = tid >> 3;
    const int fq  = tid & 7;
    int rws[AIT];
#pragma unroll
    for (int i = 0; i < AIT; i++) rws[i] = rowIdx[ldr + 32 * i];

    // fragment read addresses (u32 shared space)
    const uint32_t ubase = (uint32_t)__cvta_generic_to_shared(smc);
    const int Lrow = (lane & 7) + ((lane >> 3) & 1) * 8;
    const int Lk16 = (lane >> 4) & 1;
    const uint32_t aBase = ubase +
        (uint32_t)((mw * (MTILE / 2) + Lrow) * 80 + Lk16 * 16);
    const int bm = lane >> 3;
    const int bk = (bm & 1) * 8 + (lane & 7);
    const int bn = nw * 32 + (bm >> 1) * 8;
    const uint32_t bBase = ubase + (uint32_t)L::ABYTES +
        (uint32_t)(bk * 272 + bn * 2);

    float4 avA[AIT], avW[4];

#define LOADC(c)                                                              \
    {                                                                         \
        const int k0 = (c) * 32;                                              \
        _Pragma("unroll")                                                     \
        for (int i = 0; i < AIT; i++) {                                       \
            int rr = rws[i];                                                  \
            avA[i] = (rr >= 0)                                                \
                ? *(const float4*)(Ap + (size_t)rr * K + k0 + fq * 4)         \
                : make_float4(0.f, 0.f, 0.f, 0.f);                            \
        }                                                                     \
        _Pragma("unroll")                                                     \
        for (int i = 0; i < 4; i++) {                                         \
            int co = n0 + (fq + 8 * i) * 4;                                   \
            float4 s = *(const float4*)(sk  + (size_t)(k0 + ldr) * N + co);   \
            float4 t = *(const float4*)(dkd + (size_t)(k0 + ldr) * N + co);   \
            avW[i].x = s.x * t.x; avW[i].y = s.y * t.y;                       \
            avW[i].z = s.z * t.z; avW[i].w = s.w * t.w;                       \
        }                                                                     \
    }

#define STOREC(c)                                                             \
    {                                                                         \
        const int buf = (c) & 1;                                              \
        _Pragma("unroll")                                                     \
        for (int i = 0; i < AIT; i++) {                                       \
            int row = ldr + 32 * i;                                           \
            char* ph = smc + (buf * 2 + 0) * (MTILE * 80) + row * 80 + fq * 8;\
            char* pl = smc + (buf * 2 + 1) * (MTILE * 80) + row * 80 + fq * 8;\
            split_store(ph, pl, avA[i]);                                      \
        }                                                                     \
        _Pragma("unroll")                                                     \
        for (int i = 0; i < 4; i++) {                                         \
            char* ph = smc + L::ABYTES + (buf * 2 + 0) * 8704 +               \
                       ldr * 272 + (fq + 8 * i) * 8;                          \
            char* pl = smc + L::ABYTES + (buf * 2 + 1) * 8704 +               \
                       ldr * 272 + (fq + 8 * i) * 8;                          \
            split_store(ph, pl, avW[i]);                                      \
        }                                                                     \
    }

    LOADC(0);
    STOREC(0);

    for (int c = 0; c < NCH; c++) {
        const int buf = c & 1;
        __syncthreads();
        if (c + 1 < NCH) LOADC(c + 1);

        const uint32_t aHi = aBase + (uint32_t)((buf * 2 + 0) * (MTILE * 80));
        const uint32_t aLo = aBase + (uint32_t)((buf * 2 + 1) * (MTILE * 80));
        const uint32_t bHi = bBase + (uint32_t)((buf * 2 + 0) * 8704);
        const uint32_t bLo = bBase + (uint32_t)((buf * 2 + 1) * 8704);
#pragma unroll
        for (int ks = 0; ks < 2; ks++) {
            uint32_t ah[MT_W][4], al[MT_W][4];
#pragma unroll
            for (int mt = 0; mt < MT_W; mt++) {
                LDSM_X4(ah[mt], aHi + mt * (16 * 80) + ks * 32);
                LDSM_X4(al[mt], aLo + mt * (16 * 80) + ks * 32);
            }
            uint32_t bh[4][2], bl[4][2];
#pragma unroll
            for (int np = 0; np < 2; np++) {
                LDSM_X4T(bh[2 * np][0], bh[2 * np][1],
                         bh[2 * np + 1][0], bh[2 * np + 1][1],
                         bHi + ks * (16 * 272) + np * 32);
                LDSM_X4T(bl[2 * np][0], bl[2 * np][1],
                         bl[2 * np + 1][0], bl[2 * np + 1][1],
                         bLo + ks * (16 * 272) + np * 32);
            }
#pragma unroll
            for (int nt = 0; nt < 4; nt++) {
#pragma unroll
                for (int mt = 0; mt < MT_W; mt++) {
                    MMA_BF16(acc[mt][nt], ah[mt], bh[nt][0], bh[nt][1]);
                    MMA_BF16(acc[mt][nt], ah[mt], bl[nt][0], bl[nt][1]);
                    MMA_BF16(acc[mt][nt], al[mt], bh[nt][0], bh[nt][1]);
                }
            }
        }
        if (c + 1 < NCH) STOREC(c + 1);
    }

    // ---------------- epilogue: bias + relu + (scatter) store ----------------
#pragma unroll
    for (int mt = 0; mt < MT_W; mt++) {
#pragma unroll
        for (int half = 0; half < 2; half++) {
            int mrow = mw * (MTILE / 2) + mt * 16 + grp + half * 8;
            int r = m0 + mrow;
            if (r < len) {
                int orow = (LAYER == 2) ? g_perm[off + r] : (off + r);
                float* crow = Cp + (size_t)orow * N + n0;
#pragma unroll
                for (int nt = 0; nt < 4; nt++) {
                    int col = nw * 32 + nt * 8 + 2 * tig;
                    float2 o;
                    o.x = fmaxf(acc[mt][nt][half * 2 + 0] + biasS[col], 0.f);
                    o.y = fmaxf(acc[mt][nt][half * 2 + 1] + biasS[col + 1], 0.f);
                    *(float2*)(crow + col) = o;
                }
            }
        }
    }
}

// ---------------- launch ----------------
extern "C" void kernel_launch(void* const* d_in, const int* in_sizes, int n_in,
                              void* d_out, int out_size) {
    const float* x   = (const float*)d_in[0];
    const int*   ind = (const int*)  d_in[1];
    const float* sk0 = (const float*)d_in[2];
    const float* sb0 = (const float*)d_in[3];
    const float* dk0 = (const float*)d_in[4];
    const float* db0 = (const float*)d_in[5];
    const float* sk1 = (const float*)d_in[6];
    const float* sb1 = (const float*)d_in[7];
    const float* dk1 = (const float*)d_in[8];
    const float* db1 = (const float*)d_in[9];
    const float* sk2 = (const float*)d_in[10];
    const float* sb2 = (const float*)d_in[11];
    const float* dk2 = (const float*)d_in[12];
    const float* db2 = (const float*)d_in[13];
    float* out = (float*)d_out;

    constexpr int SM128 = SML<128>::BYTES;
    constexpr int SM64  = SML<64>::BYTES;
    cudaFuncSetAttribute(gemm_mma<0, 128>, cudaFuncAttributeMaxDynamicSharedMemorySize, SM128);
    cudaFuncSetAttribute(gemm_mma<1, 128>, cudaFuncAttributeMaxDynamicSharedMemorySize, SM128);
    cudaFuncSetAttribute(gemm_mma<2, 64>,  cudaFuncAttributeMaxDynamicSharedMemorySize, SM64);

    build_perm<<<1, 256>>>(ind);

    gemm_mma<0, 128><<<dim3(D1 / 128, MAXT128), 256, SM128>>>(x, sk0, dk0, sb0, db0, nullptr);
    gemm_mma<1, 128><<<dim3(D2 / 128, MAXT128), 256, SM128>>>(nullptr, sk1, dk1, sb1, db1, nullptr);
    gemm_mma<2, 64><<<dim3(D3 / 128, MAXT64), 256, SM64>>>(nullptr, sk2, dk2, sb2, db2, out);
}

// round 10
// speedup vs baseline: 1.8148x; 1.1481x over previous
#include <cuda_runtime.h>
#include <cuda_bf16.h>
#include <cstdint>

// Problem constants
#define B_ROWS 4096
#define NDOM 8
#define D0 1024
#define D1 1024
#define D2 512
#define D3 256
#define MAXT64 72
#define MTILE 64

// ---------------- device scratch ----------------
__device__ int   g_perm[B_ROWS];
__device__ int   g_off[NDOM + 1];
__device__ int   g_tile_d64[MAXT64];
__device__ int   g_tile_m64[MAXT64];
__device__ int   g_nt64;
__device__ float g_h1[B_ROWS * D1];
__device__ float g_h2[B_ROWS * D2];

#define MMA_BF16(d, a, b0, b1)                                                \
    asm volatile(                                                             \
        "mma.sync.aligned.m16n8k16.row.col.f32.bf16.bf16.f32 "                \
        "{%0,%1,%2,%3}, {%4,%5,%6,%7}, {%8,%9}, {%0,%1,%2,%3};"               \
        : "+f"((d)[0]), "+f"((d)[1]), "+f"((d)[2]), "+f"((d)[3])              \
        : "r"((a)[0]), "r"((a)[1]), "r"((a)[2]), "r"((a)[3]),                 \
          "r"(b0), "r"(b1))

#define LDSM_X4(r, addr)                                                      \
    asm volatile("ldmatrix.sync.aligned.m8n8.x4.shared.b16 "                  \
                 "{%0,%1,%2,%3}, [%4];"                                       \
                 : "=r"((r)[0]), "=r"((r)[1]), "=r"((r)[2]), "=r"((r)[3])     \
                 : "r"(addr))

#define LDSM_X4T(r0, r1, r2, r3, addr)                                        \
    asm volatile("ldmatrix.sync.aligned.m8n8.x4.trans.shared.b16 "            \
                 "{%0,%1,%2,%3}, [%4];"                                       \
                 : "=r"(r0), "=r"(r1), "=r"(r2), "=r"(r3)                     \
                 : "r"(addr))

__device__ __forceinline__ void split_store(char* pHi, char* pLo, float4 v) {
    __nv_bfloat162 h01 = __floats2bfloat162_rn(v.x, v.y);
    __nv_bfloat162 h23 = __floats2bfloat162_rn(v.z, v.w);
    float2 f01 = __bfloat1622float2(h01);
    float2 f23 = __bfloat1622float2(h23);
    __nv_bfloat162 l01 = __floats2bfloat162_rn(v.x - f01.x, v.y - f01.y);
    __nv_bfloat162 l23 = __floats2bfloat162_rn(v.z - f23.x, v.w - f23.y);
    uint2 hv, lv;
    hv.x = *(uint32_t*)&h01; hv.y = *(uint32_t*)&h23;
    lv.x = *(uint32_t*)&l01; lv.y = *(uint32_t*)&l23;
    *(uint2*)pHi = hv;
    *(uint2*)pLo = lv;
}

// ---------------- permutation + tile list ----------------
__global__ void build_perm(const int* __restrict__ ind) {
    __shared__ int cnt[NDOM];
    __shared__ int cur[NDOM];
    int t = threadIdx.x;
    if (t < NDOM) cnt[t] = 0;
    __syncthreads();
    for (int i = t; i < B_ROWS; i += blockDim.x) atomicAdd(&cnt[ind[i]], 1);
    __syncthreads();
    if (t == 0) {
        int s = 0;
        for (int d = 0; d < NDOM; d++) { g_off[d] = s; cur[d] = s; s += cnt[d]; }
        g_off[NDOM] = s;
        int n64 = 0;
        for (int d = 0; d < NDOM; d++) {
            int len = g_off[d + 1] - g_off[d];
            for (int m0 = 0; m0 < len; m0 += MTILE) {
                g_tile_d64[n64] = d; g_tile_m64[n64] = m0; n64++;
            }
        }
        g_nt64 = n64;
    }
    __syncthreads();
    for (int i = t; i < B_ROWS; i += blockDim.x) {
        int d = ind[i];
        int p = atomicAdd(&cur[d], 1);
        g_perm[p] = i;
    }
}

// ---------------- smem layout (bytes) ----------------
// A: [buf][split][row<64] rows of 32 bf16 (64B data, 80B stride)
// B: [buf][split][k<32]   rows of 128 bf16 (256B data, 272B stride)
#define ABYTES (4 * MTILE * 80)           // 20480
#define BBYTES (4 * 32 * 272)             // 34816
#define SM_RI  (ABYTES + BBYTES)
#define SM_BI  (SM_RI + MTILE * 4)
#define GEMM_SMEM (SM_BI + 512)           // ~56 KB -> 2 CTAs/SM

// ---------------- bf16 split (3-product) grouped GEMM ----------------
// Block tile 64 x 128, K-chunk 32, double-buffered, 256 threads / 8 warps
// (2M x 4N), warp tile 32 x 32. Fragments via ldmatrix. 2 CTAs per SM.
template <int LAYER>
__global__ __launch_bounds__(256, 2)
void gemm_mma(const float* __restrict__ xin, const float* __restrict__ sk,
              const float* __restrict__ dkk, const float* __restrict__ sb,
              const float* __restrict__ db, float* __restrict__ outp) {
    constexpr int K = (LAYER == 0) ? D0 : (LAYER == 1) ? D1 : D2;
    constexpr int N = (LAYER == 0) ? D1 : (LAYER == 1) ? D2 : D3;
    constexpr int NCH = K / 32;
    constexpr int MT_W = MTILE / 32;     // 2 m16 tiles per warp
    constexpr int AIT = MTILE / 32;      // 2 A loader items per thread

    const int tyb = blockIdx.y;
    if (tyb >= g_nt64) return;
    const int d   = g_tile_d64[tyb];
    const int m0  = g_tile_m64[tyb];
    const int off = g_off[d];
    const int len = g_off[d + 1] - off;
    const int n0  = blockIdx.x * 128;

    extern __shared__ char smc[];
    int*   rowIdx = (int*)(smc + SM_RI);
    float* biasS  = (float*)(smc + SM_BI);

    const int tid  = threadIdx.x;
    const int lane = tid & 31;
    const int w    = tid >> 5;
    const int mw   = w >> 2;
    const int nw   = w & 3;
    const int grp  = lane >> 2;
    const int tig  = lane & 3;

    if (tid < MTILE) {
        int r = m0 + tid;
        int row = -1;
        if (r < len) row = (LAYER == 0) ? g_perm[off + r] : (off + r);
        rowIdx[tid] = row;
    }
    if (tid >= 128 && tid < 160) {
        int q = tid - 128;
        float4 a = *(const float4*)(sb + n0 + q * 4);
        float4 b = *(const float4*)(db + (size_t)d * N + n0 + q * 4);
        a.x += b.x; a.y += b.y; a.z += b.z; a.w += b.w;
        *(float4*)(biasS + q * 4) = a;
    }
    __syncthreads();

    const float* Ap  = (LAYER == 0) ? xin : (LAYER == 1) ? g_h1 : g_h2;
    float*       Cp  = (LAYER == 0) ? g_h1 : (LAYER == 1) ? g_h2 : outp;
    const float* dkd = dkk + (size_t)d * K * N;

    float acc[MT_W][4][4];
#pragma unroll
    for (int i = 0; i < MT_W; i++)
#pragma unroll
        for (int j = 0; j < 4; j++)
#pragma unroll
            for (int q = 0; q < 4; q++) acc[i][j][q] = 0.f;

    // loader coords
    const int ldr = tid >> 3;
    const int fq  = tid & 7;
    int rws[AIT];
#pragma unroll
    for (int i = 0; i < AIT; i++) rws[i] = rowIdx[ldr + 32 * i];

    // fragment read addresses (u32 shared space)
    const uint32_t ubase = (uint32_t)__cvta_generic_to_shared(smc);
    const int Lrow = (lane & 7) + ((lane >> 3) & 1) * 8;
    const int Lk16 = (lane >> 4) & 1;
    const uint32_t aBase = ubase +
        (uint32_t)((mw * (MTILE / 2) + Lrow) * 80 + Lk16 * 16);
    const int bm = lane >> 3;
    const int bk = (bm & 1) * 8 + (lane & 7);
    const int bn = nw * 32 + (bm >> 1) * 8;
    const uint32_t bBase = ubase + (uint32_t)ABYTES +
        (uint32_t)(bk * 272 + bn * 2);

    float4 avA[AIT], avW[4];

#define LOADC(c)                                                              \
    {                                                                         \
        const int k0 = (c) * 32;                                              \
        _Pragma("unroll")                                                     \
        for (int i = 0; i < AIT; i++) {                                       \
            int rr = rws[i];                                                  \
            avA[i] = (rr >= 0)                                                \
                ? *(const float4*)(Ap + (size_t)rr * K + k0 + fq * 4)         \
                : make_float4(0.f, 0.f, 0.f, 0.f);                            \
        }                                                                     \
        _Pragma("unroll")                                                     \
        for (int i = 0; i < 4; i++) {                                         \
            int co = n0 + (fq + 8 * i) * 4;                                   \
            float4 s = *(const float4*)(sk  + (size_t)(k0 + ldr) * N + co);   \
            float4 t = *(const float4*)(dkd + (size_t)(k0 + ldr) * N + co);   \
            avW[i].x = s.x * t.x; avW[i].y = s.y * t.y;                       \
            avW[i].z = s.z * t.z; avW[i].w = s.w * t.w;                       \
        }                                                                     \
    }

#define STOREC(c)                                                             \
    {                                                                         \
        const int buf = (c) & 1;                                              \
        _Pragma("unroll")                                                     \
        for (int i = 0; i < AIT; i++) {                                       \
            int row = ldr + 32 * i;                                           \
            char* ph = smc + (buf * 2 + 0) * (MTILE * 80) + row * 80 + fq * 8;\
            char* pl = smc + (buf * 2 + 1) * (MTILE * 80) + row * 80 + fq * 8;\
            split_store(ph, pl, avA[i]);                                      \
        }                                                                     \
        _Pragma("unroll")                                                     \
        for (int i = 0; i < 4; i++) {                                         \
            char* ph = smc + ABYTES + (buf * 2 + 0) * 8704 +                  \
                       ldr * 272 + (fq + 8 * i) * 8;                          \
            char* pl = smc + ABYTES + (buf * 2 + 1) * 8704 +                  \
                       ldr * 272 + (fq + 8 * i) * 8;                          \
            split_store(ph, pl, avW[i]);                                      \
        }                                                                     \
    }

    LOADC(0);
    STOREC(0);

    for (int c = 0; c < NCH; c++) {
        const int buf = c & 1;
        __syncthreads();
        if (c + 1 < NCH) LOADC(c + 1);

        const uint32_t aHi = aBase + (uint32_t)((buf * 2 + 0) * (MTILE * 80));
        const uint32_t aLo = aBase + (uint32_t)((buf * 2 + 1) * (MTILE * 80));
        const uint32_t bHi = bBase + (uint32_t)((buf * 2 + 0) * 8704);
        const uint32_t bLo = bBase + (uint32_t)((buf * 2 + 1) * 8704);
#pragma unroll
        for (int ks = 0; ks < 2; ks++) {
            uint32_t ah[MT_W][4], al[MT_W][4];
#pragma unroll
            for (int mt = 0; mt < MT_W; mt++) {
                LDSM_X4(ah[mt], aHi + mt * (16 * 80) + ks * 32);
                LDSM_X4(al[mt], aLo + mt * (16 * 80) + ks * 32);
            }
            uint32_t bh[4][2], bl[4][2];
#pragma unroll
            for (int np = 0; np < 2; np++) {
                LDSM_X4T(bh[2 * np][0], bh[2 * np][1],
                         bh[2 * np + 1][0], bh[2 * np + 1][1],
                         bHi + ks * (16 * 272) + np * 32);
                LDSM_X4T(bl[2 * np][0], bl[2 * np][1],
                         bl[2 * np + 1][0], bl[2 * np + 1][1],
                         bLo + ks * (16 * 272) + np * 32);
            }
#pragma unroll
            for (int nt = 0; nt < 4; nt++) {
#pragma unroll
                for (int mt = 0; mt < MT_W; mt++) {
                    MMA_BF16(acc[mt][nt], ah[mt], bh[nt][0], bh[nt][1]);
                    MMA_BF16(acc[mt][nt], ah[mt], bl[nt][0], bl[nt][1]);
                    MMA_BF16(acc[mt][nt], al[mt], bh[nt][0], bh[nt][1]);
                }
            }
        }
        if (c + 1 < NCH) STOREC(c + 1);
    }

    // ---------------- epilogue: bias + relu + (scatter) store ----------------
#pragma unroll
    for (int mt = 0; mt < MT_W; mt++) {
#pragma unroll
        for (int half = 0; half < 2; half++) {
            int mrow = mw * (MTILE / 2) + mt * 16 + grp + half * 8;
            int r = m0 + mrow;
            if (r < len) {
                int orow = (LAYER == 2) ? g_perm[off + r] : (off + r);
                float* crow = Cp + (size_t)orow * N + n0;
#pragma unroll
                for (int nt = 0; nt < 4; nt++) {
                    int col = nw * 32 + nt * 8 + 2 * tig;
                    float2 o;
                    o.x = fmaxf(acc[mt][nt][half * 2 + 0] + biasS[col], 0.f);
                    o.y = fmaxf(acc[mt][nt][half * 2 + 1] + biasS[col + 1], 0.f);
                    *(float2*)(crow + col) = o;
                }
            }
        }
    }
}

// ---------------- launch ----------------
extern "C" void kernel_launch(void* const* d_in, const int* in_sizes, int n_in,
                              void* d_out, int out_size) {
    const float* x   = (const float*)d_in[0];
    const int*   ind = (const int*)  d_in[1];
    const float* sk0 = (const float*)d_in[2];
    const float* sb0 = (const float*)d_in[3];
    const float* dk0 = (const float*)d_in[4];
    const float* db0 = (const float*)d_in[5];
    const float* sk1 = (const float*)d_in[6];
    const float* sb1 = (const float*)d_in[7];
    const float* dk1 = (const float*)d_in[8];
    const float* db1 = (const float*)d_in[9];
    const float* sk2 = (const float*)d_in[10];
    const float* sb2 = (const float*)d_in[11];
    const float* dk2 = (const float*)d_in[12];
    const float* db2 = (const float*)d_in[13];
    float* out = (float*)d_out;

    cudaFuncSetAttribute(gemm_mma<0>, cudaFuncAttributeMaxDynamicSharedMemorySize, GEMM_SMEM);
    cudaFuncSetAttribute(gemm_mma<1>, cudaFuncAttributeMaxDynamicSharedMemorySize, GEMM_SMEM);
    cudaFuncSetAttribute(gemm_mma<2>, cudaFuncAttributeMaxDynamicSharedMemorySize, GEMM_SMEM);

    build_perm<<<1, 256>>>(ind);

    gemm_mma<0><<<dim3(D1 / 128, MAXT64), 256, GEMM_SMEM>>>(x, sk0, dk0, sb0, db0, nullptr);
    gemm_mma<1><<<dim3(D2 / 128, MAXT64), 256, GEMM_SMEM>>>(nullptr, sk1, dk1, sb1, db1, nullptr);
    gemm_mma<2><<<dim3(D3 / 128, MAXT64), 256, GEMM_SMEM>>>(nullptr, sk2, dk2, sb2, db2, out);
}